// round 1
// baseline (speedup 1.0000x reference)
#include <cuda_runtime.h>

// Problem constants (from reference): N = rows of W, M = cols of W.
#define NN 4096
#define MM 4096
#define NEG_SLOPE 0.01f

// One block per row of W. 256 threads, each handles 4 float4s (16 floats)
// => 256*16 = 4096 = MM columns. Computes the two sign-split dot products
// against the input box [l0, u0], then applies the per-neuron leaky-relu
// relaxation coefficients in the epilogue.
__global__ void __launch_bounds__(256, 4)
abstract_leaky_relu_kernel(const float* __restrict__ lowerBound,
                           const float* __restrict__ upperBound,
                           const float* __restrict__ alpha,
                           const float* __restrict__ W,
                           const float* __restrict__ b,
                           const float* __restrict__ l0,
                           const float* __restrict__ u0,
                           float* __restrict__ out)
{
    const int row = blockIdx.x;
    const int tid = threadIdx.x;

    const float4* __restrict__ Wr = reinterpret_cast<const float4*>(W + (size_t)row * MM);
    const float4* __restrict__ L4 = reinterpret_cast<const float4*>(l0);
    const float4* __restrict__ U4 = reinterpret_cast<const float4*>(u0);

    float up = 0.0f;  // max(W,0)@u0 + min(W,0)@l0
    float lo = 0.0f;  // max(W,0)@l0 + min(W,0)@u0

    #pragma unroll
    for (int k = 0; k < MM / (256 * 4); ++k) {
        const int idx = k * 256 + tid;
        const float4 w  = Wr[idx];
        const float4 lv = L4[idx];
        const float4 uv = U4[idx];

        float wp, wn;
        wp = fmaxf(w.x, 0.0f); wn = fminf(w.x, 0.0f);
        up = fmaf(wp, uv.x, up); up = fmaf(wn, lv.x, up);
        lo = fmaf(wp, lv.x, lo); lo = fmaf(wn, uv.x, lo);

        wp = fmaxf(w.y, 0.0f); wn = fminf(w.y, 0.0f);
        up = fmaf(wp, uv.y, up); up = fmaf(wn, lv.y, up);
        lo = fmaf(wp, lv.y, lo); lo = fmaf(wn, uv.y, lo);

        wp = fmaxf(w.z, 0.0f); wn = fminf(w.z, 0.0f);
        up = fmaf(wp, uv.z, up); up = fmaf(wn, lv.z, up);
        lo = fmaf(wp, lv.z, lo); lo = fmaf(wn, uv.z, lo);

        wp = fmaxf(w.w, 0.0f); wn = fminf(w.w, 0.0f);
        up = fmaf(wp, uv.w, up); up = fmaf(wn, lv.w, up);
        lo = fmaf(wp, lv.w, lo); lo = fmaf(wn, uv.w, lo);
    }

    // Warp reduction of (up, lo)
    #pragma unroll
    for (int off = 16; off > 0; off >>= 1) {
        up += __shfl_down_sync(0xFFFFFFFFu, up, off);
        lo += __shfl_down_sync(0xFFFFFFFFu, lo, off);
    }

    __shared__ float s_up[8];
    __shared__ float s_lo[8];
    const int warp = tid >> 5;
    const int lane = tid & 31;
    if (lane == 0) { s_up[warp] = up; s_lo[warp] = lo; }
    __syncthreads();

    if (tid == 0) {
        float up_t = 0.0f, lo_t = 0.0f;
        #pragma unroll
        for (int wI = 0; wI < 8; ++wI) { up_t += s_up[wI]; lo_t += s_lo[wI]; }

        const float l_i = lowerBound[row];
        const float u_i = upperBound[row];
        const float ns = NEG_SLOPE;

        float lw, uw, ubias = 0.0f;
        if (l_i > 0.0f) {
            lw = 1.0f; uw = 1.0f;
        } else if (l_i < 0.0f && u_i > 0.0f) {
            const float slope = (u_i - ns * l_i) / (u_i - l_i);
            uw = slope;
            ubias = (ns - slope) * l_i;
            lw = fminf(fmaxf(alpha[row], ns), 1.0f);
        } else {
            lw = ns; uw = ns;
        }

        const float bi = b[row];
        out[row]      = lw * (lo_t + bi);             // lower
        out[NN + row] = uw * (up_t + bi) + ubias;     // upper
    }
}

extern "C" void kernel_launch(void* const* d_in, const int* in_sizes, int n_in,
                              void* d_out, int out_size)
{
    // metadata order: lowerBound, upperBound, alpha, W, b, l0, u0
    const float* lowerBound = (const float*)d_in[0];
    const float* upperBound = (const float*)d_in[1];
    const float* alpha      = (const float*)d_in[2];
    const float* W          = (const float*)d_in[3];
    const float* b          = (const float*)d_in[4];
    const float* l0         = (const float*)d_in[5];
    const float* u0         = (const float*)d_in[6];
    float* out = (float*)d_out;

    abstract_leaky_relu_kernel<<<NN, 256>>>(lowerBound, upperBound, alpha,
                                            W, b, l0, u0, out);
}

// round 2
// speedup vs baseline: 1.1189x; 1.1189x over previous
#include <cuda_runtime.h>

#define NN 4096
#define MM 4096
#define NEG_SLOPE 0.01f

// Warp-per-2-rows, barrier-free streaming kernel.
// Identity: with s=l+u, d=u-l (d>=0):
//   up = sum max(w,0)*u + min(w,0)*l = 0.5*( sum w*s + sum |w|*d )
//   lo = sum max(w,0)*l + min(w,0)*u = 0.5*( sum w*s - sum |w|*d )
// Each warp accumulates (sc, sd) for two rows sharing the box loads.
__global__ void __launch_bounds__(64)
abstract_leaky_relu_kernel(const float* __restrict__ lowerBound,
                           const float* __restrict__ upperBound,
                           const float* __restrict__ alpha,
                           const float* __restrict__ W,
                           const float* __restrict__ b,
                           const float* __restrict__ l0,
                           const float* __restrict__ u0,
                           float* __restrict__ out)
{
    const int warp = threadIdx.x >> 5;
    const int lane = threadIdx.x & 31;
    const int row0 = (blockIdx.x * 2 + warp) * 2;   // 2 warps/block, 2 rows/warp
    const int row1 = row0 + 1;

    const float4* __restrict__ W0 = reinterpret_cast<const float4*>(W + (size_t)row0 * MM);
    const float4* __restrict__ W1 = reinterpret_cast<const float4*>(W + (size_t)row1 * MM);
    const float4* __restrict__ L4 = reinterpret_cast<const float4*>(l0);
    const float4* __restrict__ U4 = reinterpret_cast<const float4*>(u0);

    float sc0 = 0.f, sd0 = 0.f, sc1 = 0.f, sd1 = 0.f;

    #pragma unroll 4
    for (int i = 0; i < MM / 4 / 32; ++i) {
        const int idx = i * 32 + lane;
        const float4 a  = __ldcs(W0 + idx);   // streaming: don't pollute L1
        const float4 c  = __ldcs(W1 + idx);
        const float4 lv = L4[idx];
        const float4 uv = U4[idx];

        float s, d;
        s = lv.x + uv.x; d = uv.x - lv.x;
        sc0 = fmaf(a.x, s, sc0); sd0 = fmaf(fabsf(a.x), d, sd0);
        sc1 = fmaf(c.x, s, sc1); sd1 = fmaf(fabsf(c.x), d, sd1);

        s = lv.y + uv.y; d = uv.y - lv.y;
        sc0 = fmaf(a.y, s, sc0); sd0 = fmaf(fabsf(a.y), d, sd0);
        sc1 = fmaf(c.y, s, sc1); sd1 = fmaf(fabsf(c.y), d, sd1);

        s = lv.z + uv.z; d = uv.z - lv.z;
        sc0 = fmaf(a.z, s, sc0); sd0 = fmaf(fabsf(a.z), d, sd0);
        sc1 = fmaf(c.z, s, sc1); sd1 = fmaf(fabsf(c.z), d, sd1);

        s = lv.w + uv.w; d = uv.w - lv.w;
        sc0 = fmaf(a.w, s, sc0); sd0 = fmaf(fabsf(a.w), d, sd0);
        sc1 = fmaf(c.w, s, sc1); sd1 = fmaf(fabsf(c.w), d, sd1);
    }

    // Warp-level tree reduction (no smem, no block barrier)
    #pragma unroll
    for (int off = 16; off > 0; off >>= 1) {
        sc0 += __shfl_down_sync(0xFFFFFFFFu, sc0, off);
        sd0 += __shfl_down_sync(0xFFFFFFFFu, sd0, off);
        sc1 += __shfl_down_sync(0xFFFFFFFFu, sc1, off);
        sd1 += __shfl_down_sync(0xFFFFFFFFu, sd1, off);
    }

    if (lane == 0) {
        #pragma unroll
        for (int r = 0; r < 2; ++r) {
            const int   row = r ? row1 : row0;
            const float sc  = r ? sc1 : sc0;
            const float sd  = r ? sd1 : sd0;
            const float up  = 0.5f * (sc + sd);
            const float lo  = 0.5f * (sc - sd);

            const float l_i = lowerBound[row];
            const float u_i = upperBound[row];
            const float ns  = NEG_SLOPE;

            float lw, uw, ubias = 0.0f;
            if (l_i > 0.0f) {
                lw = 1.0f; uw = 1.0f;
            } else if (l_i < 0.0f && u_i > 0.0f) {
                const float slope = (u_i - ns * l_i) / (u_i - l_i);
                uw = slope;
                ubias = (ns - slope) * l_i;
                lw = fminf(fmaxf(alpha[row], ns), 1.0f);
            } else {
                lw = ns; uw = ns;
            }

            const float bi = b[row];
            out[row]      = lw * (lo + bi);            // lower
            out[NN + row] = uw * (up + bi) + ubias;    // upper
        }
    }
}

extern "C" void kernel_launch(void* const* d_in, const int* in_sizes, int n_in,
                              void* d_out, int out_size)
{
    // metadata order: lowerBound, upperBound, alpha, W, b, l0, u0
    const float* lowerBound = (const float*)d_in[0];
    const float* upperBound = (const float*)d_in[1];
    const float* alpha      = (const float*)d_in[2];
    const float* W          = (const float*)d_in[3];
    const float* b          = (const float*)d_in[4];
    const float* l0         = (const float*)d_in[5];
    const float* u0         = (const float*)d_in[6];
    float* out = (float*)d_out;

    // 1024 blocks x 64 threads: 2 warps/block, 2 rows/warp -> 4096 rows
    abstract_leaky_relu_kernel<<<NN / 4, 64>>>(lowerBound, upperBound, alpha,
                                               W, b, l0, u0, out);
}

// round 3
// speedup vs baseline: 1.3208x; 1.1805x over previous
#include <cuda_runtime.h>

#define NN 4096
#define MM 4096
#define NEG_SLOPE 0.01f

#define ROWS_PER_BLOCK 4
#define THREADS 256
#define WARPS (THREADS / 32)
// Each warp covers MM/WARPS = 512 columns = 128 float4 = 4 lane-strided iters.
#define F4_PER_WARP (MM / 4 / WARPS)      // 128
#define ITERS (F4_PER_WARP / 32)          // 4

// Identity: s=l+u, d=u-l (d>=0):
//   up = 0.5*( sum w*s + sum |w|*d ),  lo = 0.5*( sum w*s - sum |w|*d )
__global__ void __launch_bounds__(THREADS)
abstract_leaky_relu_kernel(const float* __restrict__ lowerBound,
                           const float* __restrict__ upperBound,
                           const float* __restrict__ alpha,
                           const float* __restrict__ W,
                           const float* __restrict__ b,
                           const float* __restrict__ l0,
                           const float* __restrict__ u0,
                           float* __restrict__ out)
{
    const int warp = threadIdx.x >> 5;
    const int lane = threadIdx.x & 31;
    const int row0 = blockIdx.x * ROWS_PER_BLOCK;

    const float4* __restrict__ W0 = reinterpret_cast<const float4*>(W + (size_t)(row0 + 0) * MM);
    const float4* __restrict__ W1 = reinterpret_cast<const float4*>(W + (size_t)(row0 + 1) * MM);
    const float4* __restrict__ W2 = reinterpret_cast<const float4*>(W + (size_t)(row0 + 2) * MM);
    const float4* __restrict__ W3 = reinterpret_cast<const float4*>(W + (size_t)(row0 + 3) * MM);
    const float4* __restrict__ L4 = reinterpret_cast<const float4*>(l0);
    const float4* __restrict__ U4 = reinterpret_cast<const float4*>(u0);

    float sc0 = 0.f, sd0 = 0.f, sc1 = 0.f, sd1 = 0.f;
    float sc2 = 0.f, sd2 = 0.f, sc3 = 0.f, sd3 = 0.f;

    #pragma unroll
    for (int i = 0; i < ITERS; ++i) {
        const int idx = warp * F4_PER_WARP + i * 32 + lane;
        const float4 lv = L4[idx];
        const float4 uv = U4[idx];
        const float4 a0 = W0[idx];
        const float4 a1 = W1[idx];
        const float4 a2 = W2[idx];
        const float4 a3 = W3[idx];

        float s, d;
        s = lv.x + uv.x; d = uv.x - lv.x;
        sc0 = fmaf(a0.x, s, sc0); sd0 = fmaf(fabsf(a0.x), d, sd0);
        sc1 = fmaf(a1.x, s, sc1); sd1 = fmaf(fabsf(a1.x), d, sd1);
        sc2 = fmaf(a2.x, s, sc2); sd2 = fmaf(fabsf(a2.x), d, sd2);
        sc3 = fmaf(a3.x, s, sc3); sd3 = fmaf(fabsf(a3.x), d, sd3);

        s = lv.y + uv.y; d = uv.y - lv.y;
        sc0 = fmaf(a0.y, s, sc0); sd0 = fmaf(fabsf(a0.y), d, sd0);
        sc1 = fmaf(a1.y, s, sc1); sd1 = fmaf(fabsf(a1.y), d, sd1);
        sc2 = fmaf(a2.y, s, sc2); sd2 = fmaf(fabsf(a2.y), d, sd2);
        sc3 = fmaf(a3.y, s, sc3); sd3 = fmaf(fabsf(a3.y), d, sd3);

        s = lv.z + uv.z; d = uv.z - lv.z;
        sc0 = fmaf(a0.z, s, sc0); sd0 = fmaf(fabsf(a0.z), d, sd0);
        sc1 = fmaf(a1.z, s, sc1); sd1 = fmaf(fabsf(a1.z), d, sd1);
        sc2 = fmaf(a2.z, s, sc2); sd2 = fmaf(fabsf(a2.z), d, sd2);
        sc3 = fmaf(a3.z, s, sc3); sd3 = fmaf(fabsf(a3.z), d, sd3);

        s = lv.w + uv.w; d = uv.w - lv.w;
        sc0 = fmaf(a0.w, s, sc0); sd0 = fmaf(fabsf(a0.w), d, sd0);
        sc1 = fmaf(a1.w, s, sc1); sd1 = fmaf(fabsf(a1.w), d, sd1);
        sc2 = fmaf(a2.w, s, sc2); sd2 = fmaf(fabsf(a2.w), d, sd2);
        sc3 = fmaf(a3.w, s, sc3); sd3 = fmaf(fabsf(a3.w), d, sd3);
    }

    // Warp reduction of the 8 partials
    #pragma unroll
    for (int off = 16; off > 0; off >>= 1) {
        sc0 += __shfl_down_sync(0xFFFFFFFFu, sc0, off);
        sd0 += __shfl_down_sync(0xFFFFFFFFu, sd0, off);
        sc1 += __shfl_down_sync(0xFFFFFFFFu, sc1, off);
        sd1 += __shfl_down_sync(0xFFFFFFFFu, sd1, off);
        sc2 += __shfl_down_sync(0xFFFFFFFFu, sc2, off);
        sd2 += __shfl_down_sync(0xFFFFFFFFu, sd2, off);
        sc3 += __shfl_down_sync(0xFFFFFFFFu, sc3, off);
        sd3 += __shfl_down_sync(0xFFFFFFFFu, sd3, off);
    }

    __shared__ float s_sc[WARPS][ROWS_PER_BLOCK];
    __shared__ float s_sd[WARPS][ROWS_PER_BLOCK];
    if (lane == 0) {
        s_sc[warp][0] = sc0; s_sd[warp][0] = sd0;
        s_sc[warp][1] = sc1; s_sd[warp][1] = sd1;
        s_sc[warp][2] = sc2; s_sd[warp][2] = sd2;
        s_sc[warp][3] = sc3; s_sd[warp][3] = sd3;
    }
    __syncthreads();

    if (threadIdx.x < ROWS_PER_BLOCK) {
        const int r   = threadIdx.x;
        const int row = row0 + r;
        float sc = 0.f, sd = 0.f;
        #pragma unroll
        for (int wI = 0; wI < WARPS; ++wI) { sc += s_sc[wI][r]; sd += s_sd[wI][r]; }

        const float up = 0.5f * (sc + sd);
        const float lo = 0.5f * (sc - sd);

        const float l_i = lowerBound[row];
        const float u_i = upperBound[row];
        const float ns  = NEG_SLOPE;

        float lw, uw, ubias = 0.0f;
        if (l_i > 0.0f) {
            lw = 1.0f; uw = 1.0f;
        } else if (l_i < 0.0f && u_i > 0.0f) {
            const float slope = (u_i - ns * l_i) / (u_i - l_i);
            uw = slope;
            ubias = (ns - slope) * l_i;
            lw = fminf(fmaxf(alpha[row], ns), 1.0f);
        } else {
            lw = ns; uw = ns;
        }

        const float bi = b[row];
        out[row]      = lw * (lo + bi);            // lower
        out[NN + row] = uw * (up + bi) + ubias;    // upper
    }
}

extern "C" void kernel_launch(void* const* d_in, const int* in_sizes, int n_in,
                              void* d_out, int out_size)
{
    // metadata order: lowerBound, upperBound, alpha, W, b, l0, u0
    const float* lowerBound = (const float*)d_in[0];
    const float* upperBound = (const float*)d_in[1];
    const float* alpha      = (const float*)d_in[2];
    const float* W          = (const float*)d_in[3];
    const float* b          = (const float*)d_in[4];
    const float* l0         = (const float*)d_in[5];
    const float* u0         = (const float*)d_in[6];
    float* out = (float*)d_out;

    abstract_leaky_relu_kernel<<<NN / ROWS_PER_BLOCK, THREADS>>>(
        lowerBound, upperBound, alpha, W, b, l0, u0, out);
}

// round 4
// speedup vs baseline: 1.5409x; 1.1667x over previous
#include <cuda_runtime.h>

#define NN 4096
#define MM 4096
#define NEG_SLOPE 0.01f

#define ROWS_PER_BLOCK 4
#define THREADS 128
#define WARPS (THREADS / 32)                 // 4
#define F4_PER_WARP (MM / 4 / WARPS)         // 256 float4 per warp per row
#define ITERS (F4_PER_WARP / 32)             // 8 lane-strided iterations

// Identity: s=l+u, d=u-l (d>=0):
//   up = 0.5*( sum w*s + sum |w|*d ),  lo = 0.5*( sum w*s - sum |w|*d )
// Software-pipelined: prefetch iteration i+1's loads before computing i.
__global__ void __launch_bounds__(THREADS, 7)
abstract_leaky_relu_kernel(const float* __restrict__ lowerBound,
                           const float* __restrict__ upperBound,
                           const float* __restrict__ alpha,
                           const float* __restrict__ W,
                           const float* __restrict__ b,
                           const float* __restrict__ l0,
                           const float* __restrict__ u0,
                           float* __restrict__ out)
{
    const int warp = threadIdx.x >> 5;
    const int lane = threadIdx.x & 31;
    const int row0 = blockIdx.x * ROWS_PER_BLOCK;

    const float4* __restrict__ W0 = reinterpret_cast<const float4*>(W + (size_t)(row0 + 0) * MM);
    const float4* __restrict__ W1 = reinterpret_cast<const float4*>(W + (size_t)(row0 + 1) * MM);
    const float4* __restrict__ W2 = reinterpret_cast<const float4*>(W + (size_t)(row0 + 2) * MM);
    const float4* __restrict__ W3 = reinterpret_cast<const float4*>(W + (size_t)(row0 + 3) * MM);
    const float4* __restrict__ L4 = reinterpret_cast<const float4*>(l0);
    const float4* __restrict__ U4 = reinterpret_cast<const float4*>(u0);

    float sc0 = 0.f, sd0 = 0.f, sc1 = 0.f, sd1 = 0.f;
    float sc2 = 0.f, sd2 = 0.f, sc3 = 0.f, sd3 = 0.f;

    const int base = warp * F4_PER_WARP + lane;

    // Prologue: load iteration 0
    float4 lv = L4[base];
    float4 uv = U4[base];
    float4 a0 = W0[base];
    float4 a1 = W1[base];
    float4 a2 = W2[base];
    float4 a3 = W3[base];

    #pragma unroll
    for (int i = 0; i < ITERS; ++i) {
        // Prefetch next iteration before consuming current registers
        float4 nlv, nuv, na0, na1, na2, na3;
        if (i + 1 < ITERS) {
            const int nidx = base + (i + 1) * 32;
            nlv = L4[nidx];
            nuv = U4[nidx];
            na0 = W0[nidx];
            na1 = W1[nidx];
            na2 = W2[nidx];
            na3 = W3[nidx];
        }

        float s, d;
        s = lv.x + uv.x; d = uv.x - lv.x;
        sc0 = fmaf(a0.x, s, sc0); sd0 = fmaf(fabsf(a0.x), d, sd0);
        sc1 = fmaf(a1.x, s, sc1); sd1 = fmaf(fabsf(a1.x), d, sd1);
        sc2 = fmaf(a2.x, s, sc2); sd2 = fmaf(fabsf(a2.x), d, sd2);
        sc3 = fmaf(a3.x, s, sc3); sd3 = fmaf(fabsf(a3.x), d, sd3);

        s = lv.y + uv.y; d = uv.y - lv.y;
        sc0 = fmaf(a0.y, s, sc0); sd0 = fmaf(fabsf(a0.y), d, sd0);
        sc1 = fmaf(a1.y, s, sc1); sd1 = fmaf(fabsf(a1.y), d, sd1);
        sc2 = fmaf(a2.y, s, sc2); sd2 = fmaf(fabsf(a2.y), d, sd2);
        sc3 = fmaf(a3.y, s, sc3); sd3 = fmaf(fabsf(a3.y), d, sd3);

        s = lv.z + uv.z; d = uv.z - lv.z;
        sc0 = fmaf(a0.z, s, sc0); sd0 = fmaf(fabsf(a0.z), d, sd0);
        sc1 = fmaf(a1.z, s, sc1); sd1 = fmaf(fabsf(a1.z), d, sd1);
        sc2 = fmaf(a2.z, s, sc2); sd2 = fmaf(fabsf(a2.z), d, sd2);
        sc3 = fmaf(a3.z, s, sc3); sd3 = fmaf(fabsf(a3.z), d, sd3);

        s = lv.w + uv.w; d = uv.w - lv.w;
        sc0 = fmaf(a0.w, s, sc0); sd0 = fmaf(fabsf(a0.w), d, sd0);
        sc1 = fmaf(a1.w, s, sc1); sd1 = fmaf(fabsf(a1.w), d, sd1);
        sc2 = fmaf(a2.w, s, sc2); sd2 = fmaf(fabsf(a2.w), d, sd2);
        sc3 = fmaf(a3.w, s, sc3); sd3 = fmaf(fabsf(a3.w), d, sd3);

        lv = nlv; uv = nuv; a0 = na0; a1 = na1; a2 = na2; a3 = na3;
    }

    // Warp reduction
    #pragma unroll
    for (int off = 16; off > 0; off >>= 1) {
        sc0 += __shfl_down_sync(0xFFFFFFFFu, sc0, off);
        sd0 += __shfl_down_sync(0xFFFFFFFFu, sd0, off);
        sc1 += __shfl_down_sync(0xFFFFFFFFu, sc1, off);
        sd1 += __shfl_down_sync(0xFFFFFFFFu, sd1, off);
        sc2 += __shfl_down_sync(0xFFFFFFFFu, sc2, off);
        sd2 += __shfl_down_sync(0xFFFFFFFFu, sd2, off);
        sc3 += __shfl_down_sync(0xFFFFFFFFu, sc3, off);
        sd3 += __shfl_down_sync(0xFFFFFFFFu, sd3, off);
    }

    __shared__ float s_sc[WARPS][ROWS_PER_BLOCK];
    __shared__ float s_sd[WARPS][ROWS_PER_BLOCK];
    if (lane == 0) {
        s_sc[warp][0] = sc0; s_sd[warp][0] = sd0;
        s_sc[warp][1] = sc1; s_sd[warp][1] = sd1;
        s_sc[warp][2] = sc2; s_sd[warp][2] = sd2;
        s_sc[warp][3] = sc3; s_sd[warp][3] = sd3;
    }
    __syncthreads();

    if (threadIdx.x < ROWS_PER_BLOCK) {
        const int r   = threadIdx.x;
        const int row = row0 + r;
        float sc = 0.f, sd = 0.f;
        #pragma unroll
        for (int wI = 0; wI < WARPS; ++wI) { sc += s_sc[wI][r]; sd += s_sd[wI][r]; }

        const float up = 0.5f * (sc + sd);
        const float lo = 0.5f * (sc - sd);

        const float l_i = lowerBound[row];
        const float u_i = upperBound[row];
        const float ns  = NEG_SLOPE;

        float lw, uw, ubias = 0.0f;
        if (l_i > 0.0f) {
            lw = 1.0f; uw = 1.0f;
        } else if (l_i < 0.0f && u_i > 0.0f) {
            const float slope = (u_i - ns * l_i) / (u_i - l_i);
            uw = slope;
            ubias = (ns - slope) * l_i;
            lw = fminf(fmaxf(alpha[row], ns), 1.0f);
        } else {
            lw = ns; uw = ns;
        }

        const float bi = b[row];
        out[row]      = lw * (lo + bi);            // lower
        out[NN + row] = uw * (up + bi) + ubias;    // upper
    }
}

extern "C" void kernel_launch(void* const* d_in, const int* in_sizes, int n_in,
                              void* d_out, int out_size)
{
    // metadata order: lowerBound, upperBound, alpha, W, b, l0, u0
    const float* lowerBound = (const float*)d_in[0];
    const float* upperBound = (const float*)d_in[1];
    const float* alpha      = (const float*)d_in[2];
    const float* W          = (const float*)d_in[3];
    const float* b          = (const float*)d_in[4];
    const float* l0         = (const float*)d_in[5];
    const float* u0         = (const float*)d_in[6];
    float* out = (float*)d_out;

    abstract_leaky_relu_kernel<<<NN / ROWS_PER_BLOCK, THREADS>>>(
        lowerBound, upperBound, alpha, W, b, l0, u0, out);
}